// round 2
// baseline (speedup 1.0000x reference)
#include <cuda_runtime.h>
#include <math.h>

#define LSEQ 1024
#define DMODEL 1024
#define NHEADS 16
#define DHEAD 64
#define NLAYER 3
#define DFF 4096
#define NCLS 7

// ---------------- scratch (static device memory; no allocations) ----------------
__device__ float g_x[3 * LSEQ * DMODEL];        // 12 MB  branch activations
__device__ float g_qkv[3 * LSEQ * 3 * DMODEL];  // 36 MB
__device__ float g_attn[3 * LSEQ * DMODEL];     // 12 MB
__device__ float g_t1[3 * LSEQ * DFF];          // 48 MB  ff1 / fusion temps
__device__ float g_t2[3 * LSEQ * DMODEL];       // 12 MB  proj / ff2
__device__ float g_sc[2 * LSEQ];
__device__ float g_sp[LSEQ * DMODEL];
__device__ float g_fo[LSEQ * DMODEL];

// ---------------- x = src + sinusoidal PE, replicated to 3 branches ----------------
__global__ void add_pe_kernel(const float* __restrict__ src, float* __restrict__ x)
{
    int idx = blockIdx.x * 256 + threadIdx.x;      // L*D threads
    int row = idx >> 10;
    int d   = idx & 1023;
    float e = (float)(d & ~1) / 1024.0f;
    float denom = powf(10000.0f, e);
    float ang = (float)row / denom;
    float pe = (d & 1) ? cosf(ang) : sinf(ang);
    float v = src[idx] + pe;
    x[idx] = v;
    x[idx + LSEQ * DMODEL] = v;
    x[idx + 2 * LSEQ * DMODEL] = v;
}

// ---------------- generic SGEMM: C[z] = A[z] @ B[z] + bias[z], optional ReLU ----------------
// M fixed multiple of 128, N multiple of 128, K multiple of 16.
__global__ void __launch_bounds__(256, 2) sgemm_kernel(
    const float* __restrict__ A, long long aZ,
    const float* __restrict__ B, long long bZ,
    const float* __restrict__ bias, long long biasZ,
    float* __restrict__ C, long long cZ,
    int N, int K, int relu)
{
    __shared__ __align__(16) float As[16][128];
    __shared__ __align__(16) float Bs[16][128];

    int tid = threadIdx.x;
    long long z = blockIdx.z;
    A += z * aZ + (long long)blockIdx.y * 128 * K;
    B += z * bZ + blockIdx.x * 128;
    C += z * cZ + (long long)blockIdx.y * 128 * N + blockIdx.x * 128;
    const float* bb = bias + z * biasZ + blockIdx.x * 128;

    int arow = tid >> 1;            // 0..127
    int ak   = (tid & 1) * 8;       // 0 or 8
    int bk   = tid >> 4;            // 0..15
    int bcol = (tid & 15) * 8;      // 0..120

    int m0 = (tid >> 4) * 8;
    int n0 = (tid & 15) * 8;

    float acc[8][8];
#pragma unroll
    for (int i = 0; i < 8; i++)
#pragma unroll
        for (int j = 0; j < 8; j++) acc[i][j] = 0.f;

    // prefetch first tile into registers
    float4 pa0 = *(const float4*)(A + (long long)arow * K + ak);
    float4 pa1 = *(const float4*)(A + (long long)arow * K + ak + 4);
    float4 pb0 = *(const float4*)(B + (long long)bk * N + bcol);
    float4 pb1 = *(const float4*)(B + (long long)bk * N + bcol + 4);

    for (int kt = 0; kt < K; kt += 16) {
        // regs -> smem (A transposed)
        As[ak + 0][arow] = pa0.x; As[ak + 1][arow] = pa0.y;
        As[ak + 2][arow] = pa0.z; As[ak + 3][arow] = pa0.w;
        As[ak + 4][arow] = pa1.x; As[ak + 5][arow] = pa1.y;
        As[ak + 6][arow] = pa1.z; As[ak + 7][arow] = pa1.w;
        *(float4*)&Bs[bk][bcol]     = pb0;
        *(float4*)&Bs[bk][bcol + 4] = pb1;
        __syncthreads();

        if (kt + 16 < K) {
            pa0 = *(const float4*)(A + (long long)arow * K + kt + 16 + ak);
            pa1 = *(const float4*)(A + (long long)arow * K + kt + 16 + ak + 4);
            pb0 = *(const float4*)(B + (long long)(kt + 16 + bk) * N + bcol);
            pb1 = *(const float4*)(B + (long long)(kt + 16 + bk) * N + bcol + 4);
        }

#pragma unroll
        for (int k = 0; k < 16; k++) {
            float4 a0 = *(const float4*)&As[k][m0];
            float4 a1 = *(const float4*)&As[k][m0 + 4];
            float4 b0 = *(const float4*)&Bs[k][n0];
            float4 b1 = *(const float4*)&Bs[k][n0 + 4];
            float av[8] = {a0.x, a0.y, a0.z, a0.w, a1.x, a1.y, a1.z, a1.w};
            float bv[8] = {b0.x, b0.y, b0.z, b0.w, b1.x, b1.y, b1.z, b1.w};
#pragma unroll
            for (int i = 0; i < 8; i++)
#pragma unroll
                for (int j = 0; j < 8; j++)
                    acc[i][j] += av[i] * bv[j];
        }
        __syncthreads();
    }

    float4 bv0 = *(const float4*)(bb + n0);
    float4 bv1 = *(const float4*)(bb + n0 + 4);
#pragma unroll
    for (int i = 0; i < 8; i++) {
        float4 o0, o1;
        o0.x = acc[i][0] + bv0.x; o0.y = acc[i][1] + bv0.y;
        o0.z = acc[i][2] + bv0.z; o0.w = acc[i][3] + bv0.w;
        o1.x = acc[i][4] + bv1.x; o1.y = acc[i][5] + bv1.y;
        o1.z = acc[i][6] + bv1.z; o1.w = acc[i][7] + bv1.w;
        if (relu) {
            o0.x = fmaxf(o0.x, 0.f); o0.y = fmaxf(o0.y, 0.f);
            o0.z = fmaxf(o0.z, 0.f); o0.w = fmaxf(o0.w, 0.f);
            o1.x = fmaxf(o1.x, 0.f); o1.y = fmaxf(o1.y, 0.f);
            o1.z = fmaxf(o1.z, 0.f); o1.w = fmaxf(o1.w, 0.f);
        }
        long long off = (long long)(m0 + i) * N + n0;
        *(float4*)(C + off)     = o0;
        *(float4*)(C + off + 4) = o1;
    }
}

// ---------------- windowed flash attention with on-the-fly branch masks ----------------
// grid: (L/64, NHEADS, 3 branches), block 256. Thread layout: tq = tid>>2, part = tid&3.
__global__ void __launch_bounds__(256) attn_kernel(
    const float* __restrict__ qkv, float* __restrict__ out,
    const int* __restrict__ utt, const int* __restrict__ spkm,
    const int* __restrict__ winp)
{
    __shared__ __align__(16) float Qs[64][68];
    __shared__ __align__(16) float Ks[32][68];
    __shared__ __align__(16) float Vs[32][68];
    __shared__ float Ps[64][33];
    __shared__ int spq[64], utq[64], spkk[32], utk[32];

    int tid = threadIdx.x;
    int q0  = blockIdx.x * 64;
    int h   = blockIdx.y;
    int b   = blockIdx.z;
    int W   = winp[0];
    long long base = (long long)b * LSEQ * 3072;

    // load Q tile (pre-scaled by 1/sqrt(dh)=0.125)
#pragma unroll
    for (int i = 0; i < 4; i++) {
        int g = tid + i * 256;
        int r = g >> 4, c4 = (g & 15) * 4;
        float4 q = *(const float4*)(qkv + base + (long long)(q0 + r) * 3072 + h * 64 + c4);
        q.x *= 0.125f; q.y *= 0.125f; q.z *= 0.125f; q.w *= 0.125f;
        *(float4*)&Qs[r][c4] = q;
    }
    if (tid < 64) { spq[tid] = spkm[q0 + tid]; utq[tid] = utt[q0 + tid]; }

    int tq = tid >> 2;
    int part = tid & 3;
    int i_row = q0 + tq;

    float m = -1e30f, lsum = 0.f;
    float acc[16];
#pragma unroll
    for (int d = 0; d < 16; d++) acc[d] = 0.f;

    int jlo = q0 - W; if (jlo < 0) jlo = 0;
    int jhi = q0 + 63 + W; if (jhi > LSEQ - 1) jhi = LSEQ - 1;

    for (int j0 = jlo & ~31; j0 <= jhi; j0 += 32) {
        __syncthreads();   // guards Qs first use + prior-chunk Ks/Vs reads
#pragma unroll
        for (int i = 0; i < 2; i++) {
            int g = tid + i * 256;
            int r = g >> 4, c4 = (g & 15) * 4;
            int j = j0 + r;
            float4 kv = make_float4(0.f, 0.f, 0.f, 0.f);
            float4 vv = make_float4(0.f, 0.f, 0.f, 0.f);
            if (j < LSEQ) {
                kv = *(const float4*)(qkv + base + (long long)j * 3072 + 1024 + h * 64 + c4);
                vv = *(const float4*)(qkv + base + (long long)j * 3072 + 2048 + h * 64 + c4);
            }
            *(float4*)&Ks[r][c4] = kv;
            *(float4*)&Vs[r][c4] = vv;
        }
        if (tid < 32) {
            int j = j0 + tid;
            spkk[tid] = (j < LSEQ) ? spkm[j] : -12345;
            utk[tid]  = (j < LSEQ) ? utt[j]  : 0;
        }
        __syncthreads();

        // scores: 8 keys per thread (key = kk*4 + part, interleaved to avoid bank conflicts)
        float s[8];
#pragma unroll
        for (int kk = 0; kk < 8; kk++) s[kk] = 0.f;
#pragma unroll
        for (int c0 = 0; c0 < 64; c0 += 16) {
            float q[16];
#pragma unroll
            for (int c = 0; c < 16; c += 4) {
                float4 t = *(const float4*)&Qs[tq][c0 + c];
                q[c] = t.x; q[c + 1] = t.y; q[c + 2] = t.z; q[c + 3] = t.w;
            }
#pragma unroll
            for (int kk = 0; kk < 8; kk++) {
                int key = kk * 4 + part;
#pragma unroll
                for (int c = 0; c < 16; c += 4) {
                    float4 t = *(const float4*)&Ks[key][c0 + c];
                    s[kk] += q[c] * t.x + q[c + 1] * t.y + q[c + 2] * t.z + q[c + 3] * t.w;
                }
            }
        }

        int mu = utq[tq], ms = spq[tq];
        float cmax = -3e30f;
#pragma unroll
        for (int kk = 0; kk < 8; kk++) {
            int key = kk * 4 + part;
            int j = j0 + key;
            int d = j - i_row;
            bool ok = (j < LSEQ) && (mu != 0) && (utk[key] != 0) && (d <= W) && (d >= -W);
            if (b == 1) ok = ok && (ms == spkk[key]);
            if (b == 2) ok = ok && ((ms != spkk[key]) || (d == 0));
            if (!ok) s[kk] = -2e30f;
            cmax = fmaxf(cmax, s[kk]);
        }
        cmax = fmaxf(cmax, __shfl_xor_sync(0xffffffffu, cmax, 1));
        cmax = fmaxf(cmax, __shfl_xor_sync(0xffffffffu, cmax, 2));
        float newm = fmaxf(m, cmax);
        float alpha = __expf(m - newm);
        float psum = 0.f;
#pragma unroll
        for (int kk = 0; kk < 8; kk++) {
            float p = __expf(s[kk] - newm);
            Ps[tq][kk * 4 + part] = p;
            psum += p;
        }
        psum += __shfl_xor_sync(0xffffffffu, psum, 1);
        psum += __shfl_xor_sync(0xffffffffu, psum, 2);
        lsum = lsum * alpha + psum;
        m = newm;
#pragma unroll
        for (int d = 0; d < 16; d++) acc[d] *= alpha;
        __syncwarp();
        if (psum > 0.f) {
#pragma unroll
            for (int key = 0; key < 32; key++) {
                float p = Ps[tq][key];
#pragma unroll
                for (int c = 0; c < 16; c += 4) {
                    float4 v = *(const float4*)&Vs[key][part * 16 + c];
                    acc[c]     += p * v.x; acc[c + 1] += p * v.y;
                    acc[c + 2] += p * v.z; acc[c + 3] += p * v.w;
                }
            }
        }
    }

    float inv = (lsum > 0.f) ? 1.f / lsum : 0.f;
    long long ob = ((long long)b * LSEQ + i_row) * 1024 + h * 64 + part * 16;
#pragma unroll
    for (int c = 0; c < 16; c += 4) {
        float4 v = make_float4(acc[c] * inv, acc[c + 1] * inv, acc[c + 2] * inv, acc[c + 3] * inv);
        *(float4*)(out + ob + c) = v;
    }
}

// ---------------- fused residual-add + LayerNorm (in place on x) ----------------
__global__ void __launch_bounds__(256) add_ln_kernel(
    float* __restrict__ x, const float* __restrict__ r,
    const float* __restrict__ g, const float* __restrict__ bta, int layer)
{
    __shared__ float s1[8], s2[8];
    int row = blockIdx.x;             // 0 .. 3*L-1
    int z = row >> 10;
    const float* gg = g   + ((long long)z * NLAYER + layer) * 1024;
    const float* bb = bta + ((long long)z * NLAYER + layer) * 1024;
    float* xr = x + (long long)row * 1024;
    const float* rr = r + (long long)row * 1024;
    int tid = threadIdx.x;

    float4 xv = *(const float4*)(xr + tid * 4);
    float4 rv = *(const float4*)(rr + tid * 4);
    float v0 = xv.x + rv.x, v1 = xv.y + rv.y, v2 = xv.z + rv.z, v3 = xv.w + rv.w;
    float sum = v0 + v1 + v2 + v3;
    float sq  = v0 * v0 + v1 * v1 + v2 * v2 + v3 * v3;
#pragma unroll
    for (int o = 16; o; o >>= 1) {
        sum += __shfl_xor_sync(0xffffffffu, sum, o);
        sq  += __shfl_xor_sync(0xffffffffu, sq,  o);
    }
    if ((tid & 31) == 0) { s1[tid >> 5] = sum; s2[tid >> 5] = sq; }
    __syncthreads();
    if (tid < 32) {
        sum = (tid < 8) ? s1[tid] : 0.f;
        sq  = (tid < 8) ? s2[tid] : 0.f;
#pragma unroll
        for (int o = 4; o; o >>= 1) {
            sum += __shfl_xor_sync(0xffffffffu, sum, o);
            sq  += __shfl_xor_sync(0xffffffffu, sq,  o);
        }
        if (tid == 0) { s1[0] = sum; s2[0] = sq; }
    }
    __syncthreads();
    float mean = s1[0] * (1.f / 1024.f);
    float var  = s2[0] * (1.f / 1024.f) - mean * mean;
    float rstd = rsqrtf(var + 1e-5f);
    float4 gv = *(const float4*)(gg + tid * 4);
    float4 bv = *(const float4*)(bb + tid * 4);
    float4 o;
    o.x = (v0 - mean) * rstd * gv.x + bv.x;
    o.y = (v1 - mean) * rstd * gv.y + bv.y;
    o.z = (v2 - mean) * rstd * gv.z + bv.z;
    o.w = (v3 - mean) * rstd * gv.w + bv.w;
    *(float4*)(xr + tid * 4) = o;
}

// ---------------- fusion attention: scores s[k][l] = tanh(t[k][l]) . v ----------------
__global__ void __launch_bounds__(256) fuse_score_kernel(
    const float* __restrict__ t, const float* __restrict__ v, float* __restrict__ s)
{
    __shared__ float red[8];
    int l = blockIdx.x, k = blockIdx.y, tid = threadIdx.x;
    const float* row = t + ((long long)k * LSEQ + l) * 1024;
    float4 a = *(const float4*)(row + tid * 4);
    float4 b = *(const float4*)(v + tid * 4);
    float p = tanhf(a.x) * b.x + tanhf(a.y) * b.y + tanhf(a.z) * b.z + tanhf(a.w) * b.w;
#pragma unroll
    for (int o = 16; o; o >>= 1) p += __shfl_xor_sync(0xffffffffu, p, o);
    if ((tid & 31) == 0) red[tid >> 5] = p;
    __syncthreads();
    if (tid < 32) {
        p = (tid < 8) ? red[tid] : 0.f;
#pragma unroll
        for (int o = 4; o; o >>= 1) p += __shfl_xor_sync(0xffffffffu, p, o);
        if (tid == 0) s[(long long)k * LSEQ + l] = p;
    }
}

__global__ void __launch_bounds__(256) fuse_combine_kernel(
    const float* __restrict__ h0, const float* __restrict__ h1,
    const float* __restrict__ s, float* __restrict__ out)
{
    int l = blockIdx.x, tid = threadIdx.x;
    float s0 = s[l], s1 = s[LSEQ + l];
    float mm = fmaxf(s0, s1);
    float e0 = __expf(s0 - mm), e1 = __expf(s1 - mm);
    float inv = 1.f / (e0 + e1);
    float w0 = e0 * inv, w1 = e1 * inv;
    float4 a = *(const float4*)(h0 + (long long)l * 1024 + tid * 4);
    float4 b = *(const float4*)(h1 + (long long)l * 1024 + tid * 4);
    float4 o;
    o.x = w0 * a.x + w1 * b.x; o.y = w0 * a.y + w1 * b.y;
    o.z = w0 * a.z + w1 * b.z; o.w = w0 * a.w + w1 * b.w;
    *(float4*)(out + (long long)l * 1024 + tid * 4) = o;
}

// ---------------- classifier + log_softmax ----------------
__global__ void __launch_bounds__(256) classify_kernel(
    const float* __restrict__ x, const float* __restrict__ Wc,
    const float* __restrict__ bc, float* __restrict__ out)
{
    __shared__ float red[8][8];
    int l = blockIdx.x, tid = threadIdx.x;
    const float* row = x + (long long)l * 1024;
    float p[NCLS];
#pragma unroll
    for (int c = 0; c < NCLS; c++) p[c] = 0.f;
    for (int d = tid; d < 1024; d += 256) {
        float xv = row[d];
#pragma unroll
        for (int c = 0; c < NCLS; c++) p[c] += xv * Wc[d * NCLS + c];
    }
#pragma unroll
    for (int c = 0; c < NCLS; c++)
#pragma unroll
        for (int o = 16; o; o >>= 1) p[c] += __shfl_xor_sync(0xffffffffu, p[c], o);
    if ((tid & 31) == 0)
#pragma unroll
        for (int c = 0; c < NCLS; c++) red[tid >> 5][c] = p[c];
    __syncthreads();
    if (tid == 0) {
        float lg[NCLS];
#pragma unroll
        for (int c = 0; c < NCLS; c++) {
            float a = bc[c];
#pragma unroll
            for (int w = 0; w < 8; w++) a += red[w][c];
            lg[c] = a;
        }
        float mm = lg[0];
#pragma unroll
        for (int c = 1; c < NCLS; c++) mm = fmaxf(mm, lg[c]);
        float se = 0.f;
#pragma unroll
        for (int c = 0; c < NCLS; c++) se += expf(lg[c] - mm);
        float lse = mm + logf(se);
#pragma unroll
        for (int c = 0; c < NCLS; c++) out[(long long)l * NCLS + c] = lg[c] - lse;
    }
}

// ---------------- orchestration ----------------
extern "C" void kernel_launch(void* const* d_in, const int* in_sizes, int n_in,
                              void* d_out, int out_size)
{
    const float* src  = (const float*)d_in[0];
    const int*   utt  = (const int*)d_in[1];
    const int*   spk  = (const int*)d_in[2];
    const int*   win  = (const int*)d_in[3];
    const float* Wqkv = (const float*)d_in[4];
    const float* bqkv = (const float*)d_in[5];
    const float* Wo   = (const float*)d_in[6];
    const float* bo   = (const float*)d_in[7];
    const float* ln1g = (const float*)d_in[8];
    const float* ln1b = (const float*)d_in[9];
    const float* Wf1  = (const float*)d_in[10];
    const float* bf1  = (const float*)d_in[11];
    const float* Wf2  = (const float*)d_in[12];
    const float* bf2  = (const float*)d_in[13];
    const float* ln2g = (const float*)d_in[14];
    const float* ln2b = (const float*)d_in[15];
    const float* f1W  = (const float*)d_in[16];
    const float* f1b  = (const float*)d_in[17];
    const float* f1v  = (const float*)d_in[18];
    const float* f2W  = (const float*)d_in[19];
    const float* f2b  = (const float*)d_in[20];
    const float* f2v  = (const float*)d_in[21];
    const float* clsW = (const float*)d_in[22];
    const float* clsb = (const float*)d_in[23];

    float *x, *qkv, *attn, *t1, *t2, *sc, *sp, *fo;
    cudaGetSymbolAddress((void**)&x,    g_x);
    cudaGetSymbolAddress((void**)&qkv,  g_qkv);
    cudaGetSymbolAddress((void**)&attn, g_attn);
    cudaGetSymbolAddress((void**)&t1,   g_t1);
    cudaGetSymbolAddress((void**)&t2,   g_t2);
    cudaGetSymbolAddress((void**)&sc,   g_sc);
    cudaGetSymbolAddress((void**)&sp,   g_sp);
    cudaGetSymbolAddress((void**)&fo,   g_fo);

    const long long LD = (long long)LSEQ * DMODEL;

    add_pe_kernel<<<LSEQ * DMODEL / 256, 256>>>(src, x);

    for (int l = 0; l < NLAYER; l++) {
        // QKV projection: [L,1024] x [1024,3072]
        sgemm_kernel<<<dim3(24, 8, 3), 256>>>(
            x, LD,
            Wqkv + (long long)l * 1024 * 3072, (long long)NLAYER * 1024 * 3072,
            bqkv + (long long)l * 3072,        (long long)NLAYER * 3072,
            qkv, (long long)LSEQ * 3072, 3072, 1024, 0);

        attn_kernel<<<dim3(LSEQ / 64, NHEADS, 3), 256>>>(qkv, attn, utt, spk, win);

        // output projection
        sgemm_kernel<<<dim3(8, 8, 3), 256>>>(
            attn, LD,
            Wo + (long long)l * 1024 * 1024, (long long)NLAYER * 1024 * 1024,
            bo + (long long)l * 1024,        (long long)NLAYER * 1024,
            t2, LD, 1024, 1024, 0);

        add_ln_kernel<<<3 * LSEQ, 256>>>(x, t2, ln1g, ln1b, l);

        // FFN
        sgemm_kernel<<<dim3(32, 8, 3), 256>>>(
            x, LD,
            Wf1 + (long long)l * 1024 * 4096, (long long)NLAYER * 1024 * 4096,
            bf1 + (long long)l * 4096,        (long long)NLAYER * 4096,
            t1, (long long)LSEQ * 4096, 4096, 1024, 1);

        sgemm_kernel<<<dim3(8, 8, 3), 256>>>(
            t1, (long long)LSEQ * 4096,
            Wf2 + (long long)l * 4096 * 1024, (long long)NLAYER * 4096 * 1024,
            bf2 + (long long)l * 1024,        (long long)NLAYER * 1024,
            t2, LD, 1024, 4096, 0);

        add_ln_kernel<<<3 * LSEQ, 256>>>(x, t2, ln2g, ln2b, l);
    }

    // fusion 1: over branches (sm = x[1], om = x[2])
    sgemm_kernel<<<dim3(8, 8, 2), 256>>>(x + LD, LD, f1W, 0, f1b, 0,
                                         t1, LD, 1024, 1024, 0);
    fuse_score_kernel<<<dim3(LSEQ, 2), 256>>>(t1, f1v, sc);
    fuse_combine_kernel<<<LSEQ, 256>>>(x + LD, x + 2 * LD, sc, sp);

    // fusion 2: over (ct = x[0], sp)
    sgemm_kernel<<<dim3(8, 8, 1), 256>>>(x, 0, f2W, 0, f2b, 0, t1, 0, 1024, 1024, 0);
    sgemm_kernel<<<dim3(8, 8, 1), 256>>>(sp, 0, f2W, 0, f2b, 0, t1 + LD, 0, 1024, 1024, 0);
    fuse_score_kernel<<<dim3(LSEQ, 2), 256>>>(t1, f2v, sc);
    fuse_combine_kernel<<<LSEQ, 256>>>(x, sp, sc, fo);

    classify_kernel<<<LSEQ, 256>>>(fo, clsW, clsb, (float*)d_out);
}

// round 7
// speedup vs baseline: 1.7579x; 1.7579x over previous
#include <cuda_runtime.h>
#include <cuda_bf16.h>
#include <cstdint>
#include <math.h>

#define LSEQ 1024
#define DMODEL 1024
#define NHEADS 16
#define DHEAD 64
#define NLAYER 3
#define DFF 4096
#define NCLS 7

// ===================== helpers =====================
__device__ __forceinline__ uint32_t smem_to_u32(const void* p) {
    uint32_t a;
    asm("{ .reg .u64 t; cvta.to.shared.u64 t, %1; cvt.u32.u64 %0, t; }" : "=r"(a) : "l"(p));
    return a;
}
__device__ __forceinline__ void ldsm4(uint32_t* r, uint32_t addr) {
    asm volatile("ldmatrix.sync.aligned.m8n8.x4.shared.b16 {%0,%1,%2,%3}, [%4];"
        : "=r"(r[0]), "=r"(r[1]), "=r"(r[2]), "=r"(r[3]) : "r"(addr));
}
__device__ __forceinline__ void mma_bf16(float* d, const uint32_t* a, uint32_t b0, uint32_t b1) {
    asm volatile(
        "mma.sync.aligned.m16n8k16.row.col.f32.bf16.bf16.f32 "
        "{%0,%1,%2,%3}, {%4,%5,%6,%7}, {%8,%9}, {%0,%1,%2,%3};"
        : "+f"(d[0]), "+f"(d[1]), "+f"(d[2]), "+f"(d[3])
        : "r"(a[0]), "r"(a[1]), "r"(a[2]), "r"(a[3]), "r"(b0), "r"(b1));
}

// ===================== scratch (static device memory) =====================
__device__ float g_x[3 * LSEQ * DMODEL];
__device__ float g_qkv[3 * LSEQ * 3 * DMODEL];
__device__ float g_attn[3 * LSEQ * DMODEL];
__device__ float g_t1[3 * LSEQ * DFF];
__device__ float g_t2[3 * LSEQ * DMODEL];
__device__ float g_sc[2 * LSEQ];
__device__ float g_sp[LSEQ * DMODEL];
__device__ float g_fo[LSEQ * DMODEL];
// transposed bf16 hi/lo weights: [batch][N][K]
__device__ __nv_bfloat16 g_wqkvT_h[9 * 3072 * 1024], g_wqkvT_l[9 * 3072 * 1024];
__device__ __nv_bfloat16 g_woT_h[9 * 1024 * 1024],   g_woT_l[9 * 1024 * 1024];
__device__ __nv_bfloat16 g_wf1T_h[9 * 4096 * 1024],  g_wf1T_l[9 * 4096 * 1024];
__device__ __nv_bfloat16 g_wf2T_h[9 * 1024 * 4096],  g_wf2T_l[9 * 1024 * 4096];
__device__ __nv_bfloat16 g_f1wT_h[1024 * 1024], g_f1wT_l[1024 * 1024];
__device__ __nv_bfloat16 g_f2wT_h[1024 * 1024], g_f2wT_l[1024 * 1024];

// ===================== weight transpose + hi/lo split =====================
// src: [batch][K][N] fp32 -> hi/lo: [batch][N][K] bf16
__global__ void __launch_bounds__(256) transpose_split_kernel(
    const float* __restrict__ src, __nv_bfloat16* __restrict__ hi,
    __nv_bfloat16* __restrict__ lo, int K, int N)
{
    __shared__ float t[32][33];
    long long b = blockIdx.z;
    src += b * (long long)K * N;
    hi  += b * (long long)K * N;
    lo  += b * (long long)K * N;
    int k0 = blockIdx.y * 32, n0 = blockIdx.x * 32;
    int tx = threadIdx.x, ty = threadIdx.y;   // 32 x 8
#pragma unroll
    for (int i = 0; i < 4; i++)
        t[ty + i * 8][tx] = src[(long long)(k0 + ty + i * 8) * N + n0 + tx];
    __syncthreads();
#pragma unroll
    for (int i = 0; i < 4; i++) {
        float v = t[tx][ty + i * 8];
        __nv_bfloat16 h = __float2bfloat16_rn(v);
        __nv_bfloat16 l = __float2bfloat16_rn(v - __bfloat162float(h));
        long long o = (long long)(n0 + ty + i * 8) * K + k0 + tx;
        hi[o] = h; lo[o] = l;
    }
}

// ===================== HMMA GEMM (mma.sync bf16, 3-term hi/lo split) =====================
// C[z] = A[z](fp32 [M,K]) @ B[z]^T with B stored [N,K] bf16 hi/lo; + bias, opt ReLU.
// CTA tile 128x128, K-chunk 32, double-buffered. 256 threads (8 warps = 2M x 4N).
// SMEM per buffer: Ah(10240) Al(10240) Bh(10240) Bl(10240) at 80B row pitch.
#define GEMM_SMEM_BYTES (2 * 40960)
__global__ void __launch_bounds__(256, 1) hmma_gemm_kernel(
    const float* __restrict__ A, long long aZ,
    const __nv_bfloat16* __restrict__ Bh,
    const __nv_bfloat16* __restrict__ Bl, long long bZ,
    const float* __restrict__ bias, long long biasZ,
    float* __restrict__ C, long long cZ,
    int N, int K, int relu)
{
    extern __shared__ char smem[];
    int tid = threadIdx.x;
    int wid = tid >> 5, lane = tid & 31;
    long long z = blockIdx.z;
    A  += z * aZ + (long long)blockIdx.y * 128 * K;
    Bh += z * bZ + (long long)blockIdx.x * 128 * K;
    Bl += z * bZ + (long long)blockIdx.x * 128 * K;
    C  += z * cZ + (long long)blockIdx.y * 128 * N + blockIdx.x * 128;
    const float* bb = bias + z * biasZ + blockIdx.x * 128;

    int wm = (wid & 1) * 64;       // warp M offset
    int wn = (wid >> 1) * 32;      // warp N offset

    float acc[4][4][4];
#pragma unroll
    for (int i = 0; i < 4; i++)
#pragma unroll
        for (int j = 0; j < 4; j++)
#pragma unroll
            for (int r = 0; r < 4; r++) acc[i][j][r] = 0.f;

    // load index precompute
    // A: 1024 float4-chunks: e = tid + i*256 -> r=e>>3 (row), c4=(e&7)*4 (fp32 col)
    // B: 512 16B-chunks:     e = tid + i*256 -> r=e>>2 (row), cc=e&3 (16B col)
    float4 pa[4];
    uint4 pbh[2], pbl[2];
#pragma unroll
    for (int i = 0; i < 4; i++) {
        int e = tid + (i << 8); int r = e >> 3, c4 = (e & 7) << 2;
        pa[i] = *(const float4*)(A + (long long)r * K + c4);
    }
#pragma unroll
    for (int i = 0; i < 2; i++) {
        int e = tid + (i << 8); int r = e >> 2, cc = e & 3;
        pbh[i] = *(const uint4*)(Bh + (long long)r * K + cc * 8);
        pbl[i] = *(const uint4*)(Bl + (long long)r * K + cc * 8);
    }

    const int nchunks = K >> 5;
    for (int c = 0; c < nchunks; c++) {
        char* bp = smem + (c & 1) * 40960;
        // ---- stage prefetched regs -> smem (A converted to bf16 hi/lo) ----
#pragma unroll
        for (int i = 0; i < 4; i++) {
            int e = tid + (i << 8); int r = e >> 3, c4 = (e & 7) << 2;
            float4 v = pa[i];
            __nv_bfloat162 h01 = __floats2bfloat162_rn(v.x, v.y);
            __nv_bfloat162 h23 = __floats2bfloat162_rn(v.z, v.w);
            float2 f01 = __bfloat1622float2(h01);
            float2 f23 = __bfloat1622float2(h23);
            __nv_bfloat162 l01 = __floats2bfloat162_rn(v.x - f01.x, v.y - f01.y);
            __nv_bfloat162 l23 = __floats2bfloat162_rn(v.z - f23.x, v.w - f23.y);
            uint32_t off = (uint32_t)(r * 80 + (c4 << 1));
            *(uint2*)(bp + off) =
                make_uint2(*reinterpret_cast<uint32_t*>(&h01), *reinterpret_cast<uint32_t*>(&h23));
            *(uint2*)(bp + 10240 + off) =
                make_uint2(*reinterpret_cast<uint32_t*>(&l01), *reinterpret_cast<uint32_t*>(&l23));
        }
#pragma unroll
        for (int i = 0; i < 2; i++) {
            int e = tid + (i << 8); int r = e >> 2, cc = e & 3;
            uint32_t off = (uint32_t)(r * 80 + (cc << 4));
            *(uint4*)(bp + 20480 + off) = pbh[i];
            *(uint4*)(bp + 30720 + off) = pbl[i];
        }
        __syncthreads();

        // ---- prefetch next chunk ----
        if (c + 1 < nchunks) {
            const float* An = A + ((c + 1) << 5);
            const __nv_bfloat16* Bhn = Bh + ((c + 1) << 5);
            const __nv_bfloat16* Bln = Bl + ((c + 1) << 5);
#pragma unroll
            for (int i = 0; i < 4; i++) {
                int e = tid + (i << 8); int r = e >> 3, c4 = (e & 7) << 2;
                pa[i] = *(const float4*)(An + (long long)r * K + c4);
            }
#pragma unroll
            for (int i = 0; i < 2; i++) {
                int e = tid + (i << 8); int r = e >> 2, cc = e & 3;
                pbh[i] = *(const uint4*)(Bhn + (long long)r * K + cc * 8);
                pbl[i] = *(const uint4*)(Bln + (long long)r * K + cc * 8);
            }
        }

        // ---- compute: 2 k16 steps ----
        uint32_t sa = smem_to_u32(bp);
        int lrow = lane & 15;
        int lcol = (lane >> 4) << 4;   // byte offset within 32B k-half
#pragma unroll
        for (int ks = 0; ks < 2; ks++) {
            uint32_t ah[4][4], al[4][4], bhf[2][4], blf[2][4];
#pragma unroll
            for (int mf = 0; mf < 4; mf++) {
                uint32_t ad = sa + (uint32_t)((wm + mf * 16 + lrow) * 80 + ks * 32 + lcol);
                ldsm4(ah[mf], ad);
                ldsm4(al[mf], ad + 10240);
            }
#pragma unroll
            for (int bf = 0; bf < 2; bf++) {
                uint32_t bd = sa + 20480 + (uint32_t)((wn + bf * 16 + lrow) * 80 + ks * 32 + lcol);
                ldsm4(bhf[bf], bd);
                ldsm4(blf[bf], bd + 10240);
            }
#pragma unroll
            for (int mf = 0; mf < 4; mf++)
#pragma unroll
                for (int nf = 0; nf < 4; nf++) {
                    int bf = nf >> 1, hf = nf & 1;
                    mma_bf16(acc[mf][nf], ah[mf], bhf[bf][hf], bhf[bf][hf + 2]);
                    mma_bf16(acc[mf][nf], ah[mf], blf[bf][hf], blf[bf][hf + 2]);
                    mma_bf16(acc[mf][nf], al[mf], bhf[bf][hf], bhf[bf][hf + 2]);
                }
        }
        __syncthreads();
    }

    // ---- epilogue: direct STG with bias/relu ----
    int lm = lane >> 2, ln = (lane & 3) << 1;
#pragma unroll
    for (int mf = 0; mf < 4; mf++) {
#pragma unroll
        for (int nf = 0; nf < 4; nf++) {
            int row = wm + mf * 16 + lm;
            int col = wn + nf * 8 + ln;
            float b0 = bb[col], b1 = bb[col + 1];
            float2 o0, o1;
            o0.x = acc[mf][nf][0] + b0; o0.y = acc[mf][nf][1] + b1;
            o1.x = acc[mf][nf][2] + b0; o1.y = acc[mf][nf][3] + b1;
            if (relu) {
                o0.x = fmaxf(o0.x, 0.f); o0.y = fmaxf(o0.y, 0.f);
                o1.x = fmaxf(o1.x, 0.f); o1.y = fmaxf(o1.y, 0.f);
            }
            *(float2*)(C + (long long)row * N + col) = o0;
            *(float2*)(C + (long long)(row + 8) * N + col) = o1;
        }
    }
}

// ===================== x = src + sinusoidal PE (x3 branches) =====================
__global__ void add_pe_kernel(const float* __restrict__ src, float* __restrict__ x)
{
    int idx = blockIdx.x * 256 + threadIdx.x;
    int row = idx >> 10;
    int d   = idx & 1023;
    float e = (float)(d & ~1) / 1024.0f;
    float denom = powf(10000.0f, e);
    float ang = (float)row / denom;
    float pe = (d & 1) ? cosf(ang) : sinf(ang);
    float v = src[idx] + pe;
    x[idx] = v;
    x[idx + LSEQ * DMODEL] = v;
    x[idx + 2 * LSEQ * DMODEL] = v;
}

// ===================== windowed flash attention (fp32) =====================
__global__ void __launch_bounds__(256) attn_kernel(
    const float* __restrict__ qkv, float* __restrict__ out,
    const int* __restrict__ utt, const int* __restrict__ spkm,
    const int* __restrict__ winp)
{
    __shared__ __align__(16) float Qs[64][68];
    __shared__ __align__(16) float Ks[32][68];
    __shared__ __align__(16) float Vs[32][68];
    __shared__ float Ps[64][33];
    __shared__ int spq[64], utq[64], spkk[32], utk[32];

    int tid = threadIdx.x;
    int q0  = blockIdx.x * 64;
    int h   = blockIdx.y;
    int b   = blockIdx.z;
    int W   = winp[0];
    long long base = (long long)b * LSEQ * 3072;

#pragma unroll
    for (int i = 0; i < 4; i++) {
        int g = tid + i * 256;
        int r = g >> 4, c4 = (g & 15) * 4;
        float4 q = *(const float4*)(qkv + base + (long long)(q0 + r) * 3072 + h * 64 + c4);
        q.x *= 0.125f; q.y *= 0.125f; q.z *= 0.125f; q.w *= 0.125f;
        *(float4*)&Qs[r][c4] = q;
    }
    if (tid < 64) { spq[tid] = spkm[q0 + tid]; utq[tid] = utt[q0 + tid]; }

    int tq = tid >> 2;
    int part = tid & 3;
    int i_row = q0 + tq;

    float m = -1e30f, lsum = 0.f;
    float acc[16];
#pragma unroll
    for (int d = 0; d < 16; d++) acc[d] = 0.f;

    int jlo = q0 - W; if (jlo < 0) jlo = 0;
    int jhi = q0 + 63 + W; if (jhi > LSEQ - 1) jhi = LSEQ - 1;

    for (int j0 = jlo & ~31; j0 <= jhi; j0 += 32) {
        __syncthreads();
#pragma unroll
        for (int i = 0; i < 2; i++) {
            int g = tid + i * 256;
            int r = g >> 4, c4 = (g & 15) * 4;
            int j = j0 + r;
            float4 kv = make_float4(0.f, 0.f, 0.f, 0.f);
            float4 vv = make_float4(0.f, 0.f, 0.f, 0.f);
            if (j < LSEQ) {
                kv = *(const float4*)(qkv + base + (long long)j * 3072 + 1024 + h * 64 + c4);
                vv = *(const float4*)(qkv + base + (long long)j * 3072 + 2048 + h * 64 + c4);
            }
            *(float4*)&Ks[r][c4] = kv;
            *(float4*)&Vs[r][c4] = vv;
        }
        if (tid < 32) {
            int j = j0 + tid;
            spkk[tid] = (j < LSEQ) ? spkm[j] : -12345;
            utk[tid]  = (j < LSEQ) ? utt[j]  : 0;
        }
        __syncthreads();

        float s[8];
#pragma unroll
        for (int kk = 0; kk < 8; kk++) s[kk] = 0.f;
#pragma unroll
        for (int c0 = 0; c0 < 64; c0 += 16) {
            float q[16];
#pragma unroll
            for (int c = 0; c < 16; c += 4) {
                float4 t = *(const float4*)&Qs[tq][c0 + c];
                q[c] = t.x; q[c + 1] = t.y; q[c + 2] = t.z; q[c + 3] = t.w;
            }
#pragma unroll
            for (int kk = 0; kk < 8; kk++) {
                int key = kk * 4 + part;
#pragma unroll
                for (int c = 0; c < 16; c += 4) {
                    float4 t = *(const float4*)&Ks[key][c0 + c];
                    s[kk] += q[c] * t.x + q[c + 1] * t.y + q[c + 2] * t.z + q[c + 3] * t.w;
                }
            }
        }

        int mu = utq[tq], ms = spq[tq];
        float cmax = -3e30f;
#pragma unroll
        for (int kk = 0; kk < 8; kk++) {
            int key = kk * 4 + part;
            int j = j0 + key;
            int d = j - i_row;
            bool ok = (j < LSEQ) && (mu != 0) && (utk[key] != 0) && (d <= W) && (d >= -W);
            if (b == 1) ok = ok && (ms == spkk[key]);
            if (b == 2) ok = ok && ((ms != spkk[key]) || (d == 0));
            if (!ok) s[kk] = -2e30f;
            cmax = fmaxf(cmax, s[kk]);
        }
        cmax = fmaxf(cmax, __shfl_xor_sync(0xffffffffu, cmax, 1));
        cmax = fmaxf(cmax, __shfl_xor_sync(0xffffffffu, cmax, 2));
        float newm = fmaxf(m, cmax);
        float alpha = __expf(m - newm);
        float psum = 0.f;
#pragma unroll
        for (int kk = 0; kk < 8; kk++) {
            float p = __expf(s[kk] - newm);
            Ps[tq][kk * 4 + part] = p;
            psum += p;
        }
        psum += __shfl_xor_sync(0xffffffffu, psum, 1);
        psum += __shfl_xor_sync(0xffffffffu, psum, 2);
        lsum = lsum * alpha + psum;
        m = newm;
#pragma unroll
        for (int d = 0; d < 16; d++) acc[d] *= alpha;
        __syncwarp();
        if (psum > 0.f) {
#pragma unroll
            for (int key = 0; key < 32; key++) {
                float p = Ps[tq][key];
#pragma unroll
                for (int c = 0; c < 16; c += 4) {
                    float4 v = *(const float4*)&Vs[key][part * 16 + c];
                    acc[c]     += p * v.x; acc[c + 1] += p * v.y;
                    acc[c + 2] += p * v.z; acc[c + 3] += p * v.w;
                }
            }
        }
    }

    float inv = (lsum > 0.f) ? 1.f / lsum : 0.f;
    long long ob = ((long long)b * LSEQ + i_row) * 1024 + h * 64 + part * 16;
#pragma unroll
    for (int c = 0; c < 16; c += 4) {
        float4 v = make_float4(acc[c] * inv, acc[c + 1] * inv, acc[c + 2] * inv, acc[c + 3] * inv);
        *(float4*)(out + ob + c) = v;
    }
}

// ===================== fused residual-add + LayerNorm =====================
__global__ void __launch_bounds__(256) add_ln_kernel(
    float* __restrict__ x, const float* __restrict__ r,
    const float* __restrict__ g, const float* __restrict__ bta, int layer)
{
    __shared__ float s1[8], s2[8];
    int row = blockIdx.x;
    int z = row >> 10;
    const float* gg = g   + ((long long)z * NLAYER + layer) * 1024;
    const float* bb = bta + ((long long)z * NLAYER + layer) * 1024;
    float* xr = x + (long long)row * 1024;
    const float* rr = r + (long long)row * 1024;
    int tid = threadIdx.x;

    float4 xv = *(const float4*)(xr + tid * 4);
    float4 rv = *(const float4*)(rr + tid * 4);
    float v0 = xv.x + rv.x, v1 = xv.y + rv.y, v2 = xv.z + rv.z, v3 = xv.w + rv.w;
    float sum = v0 + v1 + v2 + v3;
    float sq  = v0 * v0 + v1 * v1 + v2 * v2 + v3 * v3;
#pragma unroll
    for (int o = 16; o; o >>= 1) {
        sum += __shfl_xor_sync(0xffffffffu, sum, o);
        sq  += __shfl_xor_sync(0xffffffffu, sq,  o);
    }
    if ((tid & 31) == 0) { s1[tid >> 5] = sum; s2[tid >> 5] = sq; }
    __syncthreads();
    if (tid < 32) {
        sum = (tid < 8) ? s1[tid] : 0.f;
        sq  = (tid < 8) ? s2[tid] : 0.f;
#pragma unroll
        for (int o = 4; o; o >>= 1) {
            sum += __shfl_xor_sync(0xffffffffu, sum, o);
            sq  += __shfl_xor_sync(0xffffffffu, sq,  o);
        }
        if (tid == 0) { s1[0] = sum; s2[0] = sq; }
    }
    __syncthreads();
    float mean = s1[0] * (1.f / 1024.f);
    float var  = s2[0] * (1.f / 1024.f) - mean * mean;
    float rstd = rsqrtf(var + 1e-5f);
    float4 gv = *(const float4*)(gg + tid * 4);
    float4 bv = *(const float4*)(bb + tid * 4);
    float4 o;
    o.x = (v0 - mean) * rstd * gv.x + bv.x;
    o.y = (v1 - mean) * rstd * gv.y + bv.y;
    o.z = (v2 - mean) * rstd * gv.z + bv.z;
    o.w = (v3 - mean) * rstd * gv.w + bv.w;
    *(float4*)(xr + tid * 4) = o;
}

// ===================== fusion attention =====================
__global__ void __launch_bounds__(256) fuse_score_kernel(
    const float* __restrict__ t, const float* __restrict__ v, float* __restrict__ s)
{
    __shared__ float red[8];
    int l = blockIdx.x, k = blockIdx.y, tid = threadIdx.x;
    const float* row = t + ((long long)k * LSEQ + l) * 1024;
    float4 a = *(const float4*)(row + tid * 4);
    float4 b = *(const float4*)(v + tid * 4);
    float p = tanhf(a.x) * b.x + tanhf(a.y) * b.y + tanhf(a.z) * b.z + tanhf(a.w) * b.w;
#pragma unroll
    for (int o = 16; o; o >>= 1) p += __shfl_xor_sync(0xffffffffu, p, o);
    if ((tid & 31) == 0) red[tid >> 5] = p;
    __syncthreads();
    if (tid < 32) {
        p = (tid < 8) ? red[tid] : 0.f;
#pragma unroll
        for (int o = 4; o; o >>= 1) p += __shfl_xor_sync(0xffffffffu, p, o);
        if (tid == 0) s[(long long)k * LSEQ + l] = p;
    }
}

__global__ void __launch_bounds__(256) fuse_combine_kernel(
    const float* __restrict__ h0, const float* __restrict__ h1,
    const float* __restrict__ s, float* __restrict__ out)
{
    int l = blockIdx.x, tid = threadIdx.x;
    float s0 = s[l], s1 = s[LSEQ + l];
    float mm = fmaxf(s0, s1);
    float e0 = __expf(s0 - mm), e1 = __expf(s1 - mm);
    float inv = 1.f / (e0 + e1);
    float w0 = e0 * inv, w1 = e1 * inv;
    float4 a = *(const float4*)(h0 + (long long)l * 1024 + tid * 4);
    float4 b = *(const float4*)(h1 + (long long)l * 1024 + tid * 4);
    float4 o;
    o.x = w0 * a.x + w1 * b.x; o.y = w0 * a.y + w1 * b.y;
    o.z = w0 * a.z + w1 * b.z; o.w = w0 * a.w + w1 * b.w;
    *(float4*)(out + (long long)l * 1024 + tid * 4) = o;
}

// ===================== classifier + log_softmax =====================
__global__ void __launch_bounds__(256) classify_kernel(
    const float* __restrict__ x, const float* __restrict__ Wc,
    const float* __restrict__ bc, float* __restrict__ out)
{
    __shared__ float red[8][8];
    int l = blockIdx.x, tid = threadIdx.x;
    const float* row = x + (long long)l * 1024;
    float p[NCLS];
#pragma unroll
    for (int c = 0; c < NCLS; c++) p[c] = 0.f;
    for (int d = tid; d < 1024; d += 256) {
        float xv = row[d];
#pragma unroll
        for (int c = 0; c < NCLS; c++) p[c] += xv * Wc[d * NCLS + c];
    }
#pragma unroll
    for (int c = 0; c < NCLS; c++)
#pragma unroll
        for (int o = 16; o; o >>= 1) p[c] += __shfl_xor_sync(0xffffffffu, p[c], o);
    if ((tid & 31) == 0)
#pragma unroll
        for (int c = 0; c < NCLS; c++) red[tid >> 5][c] = p[c];
    __syncthreads();
    if (tid == 0) {
        float lg[NCLS];
#pragma unroll
        for (int c = 0; c < NCLS; c++) {
            float a = bc[c];
#pragma unroll
            for (int w = 0; w < 8; w++) a += red[w][c];
            lg[c] = a;
        }
        float mm = lg[0];
#pragma unroll
        for (int c = 1; c < NCLS; c++) mm = fmaxf(mm, lg[c]);
        float se = 0.f;
#pragma unroll
        for (int c = 0; c < NCLS; c++) se += expf(lg[c] - mm);
        float lse = mm + logf(se);
#pragma unroll
        for (int c = 0; c < NCLS; c++) out[(long long)l * NCLS + c] = lg[c] - lse;
    }
}

// ===================== orchestration =====================
extern "C" void kernel_launch(void* const* d_in, const int* in_sizes, int n_in,
                              void* d_out, int out_size)
{
    const float* src  = (const float*)d_in[0];
    const int*   utt  = (const int*)d_in[1];
    const int*   spk  = (const int*)d_in[2];
    const int*   win  = (const int*)d_in[3];
    const float* Wqkv = (const float*)d_in[4];
    const float* bqkv = (const float*)d_in[5];
    const float* Wo   = (const float*)d_in[6];
    const float* bo   = (const float*)d_in[7];
    const float* ln1g = (const float*)d_in[8];
    const float* ln1b = (const float*)d_in[9];
    const float* Wf1  = (const float*)d_in[10];
    const float* bf1  = (const float*)d_in[11];
    const float* Wf2  = (const float*)d_in[12];
    const float* bf2  = (const float*)d_in[13];
    const float* ln2g = (const float*)d_in[14];
    const float* ln2b = (const float*)d_in[15];
    const float* f1W  = (const float*)d_in[16];
    const float* f1b  = (const float*)d_in[17];
    const float* f1v  = (const float*)d_in[18];
    const float* f2W  = (const float*)d_in[19];
    const float* f2b  = (const float*)d_in[20];
    const float* f2v  = (const float*)d_in[21];
    const float* clsW = (const float*)d_in[22];
    const float* clsb = (const float*)d_in[23];

    float *x, *qkv, *attn, *t1, *t2, *sc, *sp, *fo;
    cudaGetSymbolAddress((void**)&x,    g_x);
    cudaGetSymbolAddress((void**)&qkv,  g_qkv);
    cudaGetSymbolAddress((void**)&attn, g_attn);
    cudaGetSymbolAddress((void**)&t1,   g_t1);
    cudaGetSymbolAddress((void**)&t2,   g_t2);
    cudaGetSymbolAddress((void**)&sc,   g_sc);
    cudaGetSymbolAddress((void**)&sp,   g_sp);
    cudaGetSymbolAddress((void**)&fo,   g_fo);

    __nv_bfloat16 *wqkvTh, *wqkvTl, *woTh, *woTl, *wf1Th, *wf1Tl, *wf2Th, *wf2Tl;
    __nv_bfloat16 *f1wTh, *f1wTl, *f2wTh, *f2wTl;
    cudaGetSymbolAddress((void**)&wqkvTh, g_wqkvT_h);
    cudaGetSymbolAddress((void**)&wqkvTl, g_wqkvT_l);
    cudaGetSymbolAddress((void**)&woTh,   g_woT_h);
    cudaGetSymbolAddress((void**)&woTl,   g_woT_l);
    cudaGetSymbolAddress((void**)&wf1Th,  g_wf1T_h);
    cudaGetSymbolAddress((void**)&wf1Tl,  g_wf1T_l);
    cudaGetSymbolAddress((void**)&wf2Th,  g_wf2T_h);
    cudaGetSymbolAddress((void**)&wf2Tl,  g_wf2T_l);
    cudaGetSymbolAddress((void**)&f1wTh,  g_f1wT_h);
    cudaGetSymbolAddress((void**)&f1wTl,  g_f1wT_l);
    cudaGetSymbolAddress((void**)&f2wTh,  g_f2wT_h);
    cudaGetSymbolAddress((void**)&f2wTl,  g_f2wT_l);

    cudaFuncSetAttribute(hmma_gemm_kernel, cudaFuncAttributeMaxDynamicSharedMemorySize,
                         GEMM_SMEM_BYTES);

    const long long LD = (long long)LSEQ * DMODEL;
    dim3 tb(32, 8);

    // weight conversion (transpose + bf16 hi/lo split)
    transpose_split_kernel<<<dim3(96, 32, 9),   tb>>>(Wqkv, wqkvTh, wqkvTl, 1024, 3072);
    transpose_split_kernel<<<dim3(32, 32, 9),   tb>>>(Wo,   woTh,   woTl,   1024, 1024);
    transpose_split_kernel<<<dim3(128, 32, 9),  tb>>>(Wf1,  wf1Th,  wf1Tl,  1024, 4096);
    transpose_split_kernel<<<dim3(32, 128, 9),  tb>>>(Wf2,  wf2Th,  wf2Tl,  4096, 1024);
    transpose_split_kernel<<<dim3(32, 32, 1),   tb>>>(f1W,  f1wTh,  f1wTl,  1024, 1024);
    transpose_split_kernel<<<dim3(32, 32, 1),   tb>>>(f2W,  f2wTh,  f2wTl,  1024, 1024);

    add_pe_kernel<<<LSEQ * DMODEL / 256, 256>>>(src, x);

    for (int l = 0; l < NLAYER; l++) {
        // QKV: [L,1024] x W[1024,3072]
        hmma_gemm_kernel<<<dim3(24, 8, 3), 256, GEMM_SMEM_BYTES>>>(
            x, LD,
            wqkvTh + (long long)l * 3072 * 1024, wqkvTl + (long long)l * 3072 * 1024,
            (long long)NLAYER * 3072 * 1024,
            bqkv + (long long)l * 3072, (long long)NLAYER * 3072,
            qkv, (long long)LSEQ * 3072, 3072, 1024, 0);

        attn_kernel<<<dim3(LSEQ / 64, NHEADS, 3), 256>>>(qkv, attn, utt, spk, win);

        hmma_gemm_kernel<<<dim3(8, 8, 3), 256, GEMM_SMEM_BYTES>>>(
            attn, LD,
            woTh + (long long)l * 1024 * 1024, woTl + (long long)l * 1024 * 1024,
            (long long)NLAYER * 1024 * 1024,
            bo + (long long)l * 1024, (long long)NLAYER * 1024,
            t2, LD, 1024, 1024, 0);

        add_ln_kernel<<<3 * LSEQ, 256>>>(x, t2, ln1g, ln1b, l);

        hmma_gemm_kernel<<<dim3(32, 8, 3), 256, GEMM_SMEM_BYTES>>>(
            x, LD,
            wf1Th + (long long)l * 4096 * 1024, wf1Tl + (long long)l * 4096 * 1024,
            (long long)NLAYER * 4096 * 1024,
            bf1 + (long long)l * 4096, (long long)NLAYER * 4096,
            t1, (long long)LSEQ * 4096, 4096, 1024, 1);

        hmma_gemm_kernel<<<dim3(8, 8, 3), 256, GEMM_SMEM_BYTES>>>(
            t1, (long long)LSEQ * 4096,
            wf2Th + (long long)l * 1024 * 4096, wf2Tl + (long long)l * 1024 * 4096,
            (long long)NLAYER * 1024 * 4096,
            bf2 + (long long)l * 1024, (long long)NLAYER * 1024,
            t2, LD, 1024, 4096, 0);

        add_ln_kernel<<<3 * LSEQ, 256>>>(x, t2, ln2g, ln2b, l);
    }

    // fusion 1: branches sm, om
    hmma_gemm_kernel<<<dim3(8, 8, 2), 256, GEMM_SMEM_BYTES>>>(
        x + LD, LD, f1wTh, f1wTl, 0, f1b, 0, t1, LD, 1024, 1024, 0);
    fuse_score_kernel<<<dim3(LSEQ, 2), 256>>>(t1, f1v, sc);
    fuse_combine_kernel<<<LSEQ, 256>>>(x + LD, x + 2 * LD, sc, sp);

    // fusion 2: ct, sp
    hmma_gemm_kernel<<<dim3(8, 8, 1), 256, GEMM_SMEM_BYTES>>>(
        x, 0, f2wTh, f2wTl, 0, f2b, 0, t1, 0, 1024, 1024, 0);
    hmma_gemm_kernel<<<dim3(8, 8, 1), 256, GEMM_SMEM_BYTES>>>(
        sp, 0, f2wTh, f2wTl, 0, f2b, 0, t1 + LD, 0, 1024, 1024, 0);
    fuse_score_kernel<<<dim3(LSEQ, 2), 256>>>(t1, f2v, sc);
    fuse_combine_kernel<<<LSEQ, 256>>>(x, sp, sc, fo);

    classify_kernel<<<LSEQ, 256>>>(fo, clsW, clsb, (float*)d_out);
}

// round 9
// speedup vs baseline: 1.8443x; 1.0492x over previous
#include <cuda_runtime.h>
#include <cuda_bf16.h>
#include <cstdint>
#include <math.h>

#define LSEQ 1024
#define DMODEL 1024
#define NHEADS 16
#define DHEAD 64
#define NLAYER 3
#define DFF 4096
#define NCLS 7

// ===================== helpers =====================
__device__ __forceinline__ uint32_t smem_to_u32(const void* p) {
    uint32_t a;
    asm("{ .reg .u64 t; cvta.to.shared.u64 t, %1; cvt.u32.u64 %0, t; }" : "=r"(a) : "l"(p));
    return a;
}
__device__ __forceinline__ void ldsm4(uint32_t* r, uint32_t addr) {
    asm volatile("ldmatrix.sync.aligned.m8n8.x4.shared.b16 {%0,%1,%2,%3}, [%4];"
        : "=r"(r[0]), "=r"(r[1]), "=r"(r[2]), "=r"(r[3]) : "r"(addr));
}
__device__ __forceinline__ void mma_bf16(float* d, const uint32_t* a, uint32_t b0, uint32_t b1) {
    asm volatile(
        "mma.sync.aligned.m16n8k16.row.col.f32.bf16.bf16.f32 "
        "{%0,%1,%2,%3}, {%4,%5,%6,%7}, {%8,%9}, {%0,%1,%2,%3};"
        : "+f"(d[0]), "+f"(d[1]), "+f"(d[2]), "+f"(d[3])
        : "r"(a[0]), "r"(a[1]), "r"(a[2]), "r"(a[3]), "r"(b0), "r"(b1));
}
#define CP_ASYNC_CG(dst, src) \
    asm volatile("cp.async.cg.shared.global [%0], [%1], 16;" :: "r"(dst), "l"(src))
#define CP_COMMIT() asm volatile("cp.async.commit_group;" ::: "memory")
#define CP_WAIT0()  asm volatile("cp.async.wait_group 0;" ::: "memory")

// ===================== scratch (static device memory) =====================
__device__ float g_x[3 * LSEQ * DMODEL];
__device__ float g_qkv[3 * LSEQ * 3 * DMODEL];
__device__ float g_attn[3 * LSEQ * DMODEL];
__device__ float g_t1[3 * LSEQ * DFF];
__device__ float g_t2[3 * LSEQ * DMODEL];
__device__ float g_sc[2 * LSEQ];
__device__ float g_sp[LSEQ * DMODEL];
__device__ float g_fo[LSEQ * DMODEL];
// transposed bf16 hi/lo weights: [batch][N][K]
__device__ __nv_bfloat16 g_wqkvT_h[9 * 3072 * 1024], g_wqkvT_l[9 * 3072 * 1024];
__device__ __nv_bfloat16 g_woT_h[9 * 1024 * 1024],   g_woT_l[9 * 1024 * 1024];
__device__ __nv_bfloat16 g_wf1T_h[9 * 4096 * 1024],  g_wf1T_l[9 * 4096 * 1024];
__device__ __nv_bfloat16 g_wf2T_h[9 * 1024 * 4096],  g_wf2T_l[9 * 1024 * 4096];
__device__ __nv_bfloat16 g_f1wT_h[1024 * 1024], g_f1wT_l[1024 * 1024];
__device__ __nv_bfloat16 g_f2wT_h[1024 * 1024], g_f2wT_l[1024 * 1024];

// ===================== weight transpose + hi/lo split =====================
__global__ void __launch_bounds__(256) transpose_split_kernel(
    const float* __restrict__ src, __nv_bfloat16* __restrict__ hi,
    __nv_bfloat16* __restrict__ lo, int K, int N)
{
    __shared__ float t[32][33];
    long long b = blockIdx.z;
    src += b * (long long)K * N;
    hi  += b * (long long)K * N;
    lo  += b * (long long)K * N;
    int k0 = blockIdx.y * 32, n0 = blockIdx.x * 32;
    int tx = threadIdx.x, ty = threadIdx.y;   // 32 x 8
#pragma unroll
    for (int i = 0; i < 4; i++)
        t[ty + i * 8][tx] = src[(long long)(k0 + ty + i * 8) * N + n0 + tx];
    __syncthreads();
#pragma unroll
    for (int i = 0; i < 4; i++) {
        float v = t[tx][ty + i * 8];
        __nv_bfloat16 h = __float2bfloat16_rn(v);
        __nv_bfloat16 l = __float2bfloat16_rn(v - __bfloat162float(h));
        long long o = (long long)(n0 + ty + i * 8) * K + k0 + tx;
        hi[o] = h; lo[o] = l;
    }
}

// ===================== HMMA GEMM (bf16 3-term, cp.async B, 2 CTAs/SM) =====================
// C[z] = A[z](fp32 [M,K]) @ B[z]^T, B stored [N,K] bf16 hi/lo; + bias, opt ReLU.
// CTA tile 128x128, K-chunk 32, double-buffered. 256 threads (8 warps = 2M x 4N).
// SMEM per buffer: Ah(10240) Al(10240) Bh(10240) Bl(10240), 80B row pitch.
#define GEMM_SMEM_BYTES (2 * 40960)
__global__ void __launch_bounds__(256, 2) hmma_gemm_kernel(
    const float* __restrict__ A, long long aZ,
    const __nv_bfloat16* __restrict__ Bh,
    const __nv_bfloat16* __restrict__ Bl, long long bZ,
    const float* __restrict__ bias, long long biasZ,
    float* __restrict__ C, long long cZ,
    int N, int K, int relu)
{
    extern __shared__ char smem[];
    uint32_t sbase = smem_to_u32(smem);
    int tid = threadIdx.x;
    int wid = tid >> 5, lane = tid & 31;
    long long z = blockIdx.z;
    A  += z * aZ + (long long)blockIdx.y * 128 * K;
    Bh += z * bZ + (long long)blockIdx.x * 128 * K;
    Bl += z * bZ + (long long)blockIdx.x * 128 * K;
    C  += z * cZ + (long long)blockIdx.y * 128 * N + blockIdx.x * 128;
    const float* bb = bias + z * biasZ + blockIdx.x * 128;

    int wm = (wid & 1) * 64;       // warp M offset
    int wn = (wid >> 1) * 32;      // warp N offset

    float acc[4][4][4];
#pragma unroll
    for (int i = 0; i < 4; i++)
#pragma unroll
        for (int j = 0; j < 4; j++)
#pragma unroll
            for (int r = 0; r < 4; r++) acc[i][j][r] = 0.f;

    // B cp.async indices: e = tid + i*256 -> r = e>>2 (row), cc = e&3 (16B col within 64B row)
    int br = tid >> 2, bc16 = (tid & 3) << 4;       // i=0
    // A reg-prefetch indices: e = tid + i*256 -> r=e>>3, c4=(e&7)*4
    float4 pa[4];
#pragma unroll
    for (int i = 0; i < 4; i++) {
        int e = tid + (i << 8); int r = e >> 3, c4 = (e & 7) << 2;
        pa[i] = *(const float4*)(A + (long long)r * K + c4);
    }
    // prologue: cp.async B chunk 0 -> buf 0
    {
        uint32_t d0 = sbase + 20480 + (uint32_t)(br * 80) + bc16;
#pragma unroll
        for (int i = 0; i < 2; i++) {
            int rr = br + (i << 6);
            CP_ASYNC_CG(d0 + (uint32_t)(i * 64 * 80), Bh + (long long)rr * K + (bc16 >> 1));
            CP_ASYNC_CG(d0 + 10240u + (uint32_t)(i * 64 * 80), Bl + (long long)rr * K + (bc16 >> 1));
        }
        CP_COMMIT();
    }

    const int nchunks = K >> 5;
    for (int c = 0; c < nchunks; c++) {
        uint32_t bufa = sbase + (uint32_t)((c & 1) * 40960);
        char* bp = smem + (c & 1) * 40960;
        // ---- stage A regs -> smem (convert to bf16 hi/lo) ----
#pragma unroll
        for (int i = 0; i < 4; i++) {
            int e = tid + (i << 8); int r = e >> 3, c4 = (e & 7) << 2;
            float4 v = pa[i];
            __nv_bfloat162 h01 = __floats2bfloat162_rn(v.x, v.y);
            __nv_bfloat162 h23 = __floats2bfloat162_rn(v.z, v.w);
            float2 f01 = __bfloat1622float2(h01);
            float2 f23 = __bfloat1622float2(h23);
            __nv_bfloat162 l01 = __floats2bfloat162_rn(v.x - f01.x, v.y - f01.y);
            __nv_bfloat162 l23 = __floats2bfloat162_rn(v.z - f23.x, v.w - f23.y);
            uint32_t off = (uint32_t)(r * 80 + (c4 << 1));
            *(uint2*)(bp + off) =
                make_uint2(*reinterpret_cast<uint32_t*>(&h01), *reinterpret_cast<uint32_t*>(&h23));
            *(uint2*)(bp + 10240 + off) =
                make_uint2(*reinterpret_cast<uint32_t*>(&l01), *reinterpret_cast<uint32_t*>(&l23));
        }
        CP_WAIT0();          // B for chunk c complete (this thread's)
        __syncthreads();     // all threads' A stores + B arrivals visible

        // ---- prefetch chunk c+1: A regs (LDG) + B cp.async into other buffer ----
        if (c + 1 < nchunks) {
            const float* An = A + ((c + 1) << 5);
#pragma unroll
            for (int i = 0; i < 4; i++) {
                int e = tid + (i << 8); int r = e >> 3, c4 = (e & 7) << 2;
                pa[i] = *(const float4*)(An + (long long)r * K + c4);
            }
            const __nv_bfloat16* Bhn = Bh + ((c + 1) << 5);
            const __nv_bfloat16* Bln = Bl + ((c + 1) << 5);
            uint32_t d0 = sbase + (uint32_t)(((c + 1) & 1) * 40960) + 20480
                        + (uint32_t)(br * 80) + bc16;
#pragma unroll
            for (int i = 0; i < 2; i++) {
                int rr = br + (i << 6);
                CP_ASYNC_CG(d0 + (uint32_t)(i * 64 * 80), Bhn + (long long)rr * K + (bc16 >> 1));
                CP_ASYNC_CG(d0 + 10240u + (uint32_t)(i * 64 * 80), Bln + (long long)rr * K + (bc16 >> 1));
            }
            CP_COMMIT();
        }

        // ---- compute: 2 k16 steps; A frags loaded per-mf to cap registers ----
        int lrow = lane & 15;
        int lcol = (lane >> 4) << 4;
#pragma unroll
        for (int ks = 0; ks < 2; ks++) {
            uint32_t bhf[2][4], blf[2][4];
#pragma unroll
            for (int bf = 0; bf < 2; bf++) {
                uint32_t bd = bufa + 20480 + (uint32_t)((wn + bf * 16 + lrow) * 80 + ks * 32 + lcol);
                ldsm4(bhf[bf], bd);
                ldsm4(blf[bf], bd + 10240);
            }
#pragma unroll
            for (int mf = 0; mf < 4; mf++) {
                uint32_t ah[4], al[4];
                uint32_t ad = bufa + (uint32_t)((wm + mf * 16 + lrow) * 80 + ks * 32 + lcol);
                ldsm4(ah, ad);
                ldsm4(al, ad + 10240);
#pragma unroll
                for (int nf = 0; nf < 4; nf++) {
                    int bf = nf >> 1, hf = nf & 1;
                    mma_bf16(acc[mf][nf], ah, bhf[bf][hf], bhf[bf][hf + 2]);
                    mma_bf16(acc[mf][nf], ah, blf[bf][hf], blf[bf][hf + 2]);
                    mma_bf16(acc[mf][nf], al, bhf[bf][hf], bhf[bf][hf + 2]);
                }
            }
        }
        __syncthreads();
    }

    // ---- epilogue: direct STG with bias/relu ----
    int lm = lane >> 2, ln = (lane & 3) << 1;
#pragma unroll
    for (int mf = 0; mf < 4; mf++) {
#pragma unroll
        for (int nf = 0; nf < 4; nf++) {
            int row = wm + mf * 16 + lm;
            int col = wn + nf * 8 + ln;
            float b0 = bb[col], b1 = bb[col + 1];
            float2 o0, o1;
            o0.x = acc[mf][nf][0] + b0; o0.y = acc[mf][nf][1] + b1;
            o1.x = acc[mf][nf][2] + b0; o1.y = acc[mf][nf][3] + b1;
            if (relu) {
                o0.x = fmaxf(o0.x, 0.f); o0.y = fmaxf(o0.y, 0.f);
                o1.x = fmaxf(o1.x, 0.f); o1.y = fmaxf(o1.y, 0.f);
            }
            *(float2*)(C + (long long)row * N + col) = o0;
            *(float2*)(C + (long long)(row + 8) * N + col) = o1;
        }
    }
}

// ===================== x = src + sinusoidal PE (x3 branches) =====================
__global__ void add_pe_kernel(const float* __restrict__ src, float* __restrict__ x)
{
    int idx = blockIdx.x * 256 + threadIdx.x;
    int row = idx >> 10;
    int d   = idx & 1023;
    float e = (float)(d & ~1) / 1024.0f;
    float denom = powf(10000.0f, e);
    float ang = (float)row / denom;
    float pe = (d & 1) ? cosf(ang) : sinf(ang);
    float v = src[idx] + pe;
    x[idx] = v;
    x[idx + LSEQ * DMODEL] = v;
    x[idx + 2 * LSEQ * DMODEL] = v;
}

// ===================== windowed flash attention (fp32) =====================
__global__ void __launch_bounds__(256) attn_kernel(
    const float* __restrict__ qkv, float* __restrict__ out,
    const int* __restrict__ utt, const int* __restrict__ spkm,
    const int* __restrict__ winp)
{
    __shared__ __align__(16) float Qs[64][68];
    __shared__ __align__(16) float Ks[32][68];
    __shared__ __align__(16) float Vs[32][68];
    __shared__ float Ps[64][33];
    __shared__ int spq[64], utq[64], spkk[32], utk[32];

    int tid = threadIdx.x;
    int q0  = blockIdx.x * 64;
    int h   = blockIdx.y;
    int b   = blockIdx.z;
    int W   = winp[0];
    long long base = (long long)b * LSEQ * 3072;

#pragma unroll
    for (int i = 0; i < 4; i++) {
        int g = tid + i * 256;
        int r = g >> 4, c4 = (g & 15) * 4;
        float4 q = *(const float4*)(qkv + base + (long long)(q0 + r) * 3072 + h * 64 + c4);
        q.x *= 0.125f; q.y *= 0.125f; q.z *= 0.125f; q.w *= 0.125f;
        *(float4*)&Qs[r][c4] = q;
    }
    if (tid < 64) { spq[tid] = spkm[q0 + tid]; utq[tid] = utt[q0 + tid]; }

    int tq = tid >> 2;
    int part = tid & 3;
    int i_row = q0 + tq;

    float m = -1e30f, lsum = 0.f;
    float acc[16];
#pragma unroll
    for (int d = 0; d < 16; d++) acc[d] = 0.f;

    int jlo = q0 - W; if (jlo < 0) jlo = 0;
    int jhi = q0 + 63 + W; if (jhi > LSEQ - 1) jhi = LSEQ - 1;

    for (int j0 = jlo & ~31; j0 <= jhi; j0 += 32) {
        __syncthreads();
#pragma unroll
        for (int i = 0; i < 2; i++) {
            int g = tid + i * 256;
            int r = g >> 4, c4 = (g & 15) * 4;
            int j = j0 + r;
            float4 kv = make_float4(0.f, 0.f, 0.f, 0.f);
            float4 vv = make_float4(0.f, 0.f, 0.f, 0.f);
            if (j < LSEQ) {
                kv = *(const float4*)(qkv + base + (long long)j * 3072 + 1024 + h * 64 + c4);
                vv = *(const float4*)(qkv + base + (long long)j * 3072 + 2048 + h * 64 + c4);
            }
            *(float4*)&Ks[r][c4] = kv;
            *(float4*)&Vs[r][c4] = vv;
        }
        if (tid < 32) {
            int j = j0 + tid;
            spkk[tid] = (j < LSEQ) ? spkm[j] : -12345;
            utk[tid]  = (j < LSEQ) ? utt[j]  : 0;
        }
        __syncthreads();

        float s[8];
#pragma unroll
        for (int kk = 0; kk < 8; kk++) s[kk] = 0.f;
#pragma unroll
        for (int c0 = 0; c0 < 64; c0 += 16) {
            float q[16];
#pragma unroll
            for (int c = 0; c < 16; c += 4) {
                float4 t = *(const float4*)&Qs[tq][c0 + c];
                q[c] = t.x; q[c + 1] = t.y; q[c + 2] = t.z; q[c + 3] = t.w;
            }
#pragma unroll
            for (int kk = 0; kk < 8; kk++) {
                int key = kk * 4 + part;
#pragma unroll
                for (int c = 0; c < 16; c += 4) {
                    float4 t = *(const float4*)&Ks[key][c0 + c];
                    s[kk] += q[c] * t.x + q[c + 1] * t.y + q[c + 2] * t.z + q[c + 3] * t.w;
                }
            }
        }

        int mu = utq[tq], ms = spq[tq];
        float cmax = -3e30f;
#pragma unroll
        for (int kk = 0; kk < 8; kk++) {
            int key = kk * 4 + part;
            int j = j0 + key;
            int d = j - i_row;
            bool ok = (j < LSEQ) && (mu != 0) && (utk[key] != 0) && (d <= W) && (d >= -W);
            if (b == 1) ok = ok && (ms == spkk[key]);
            if (b == 2) ok = ok && ((ms != spkk[key]) || (d == 0));
            if (!ok) s[kk] = -2e30f;
            cmax = fmaxf(cmax, s[kk]);
        }
        cmax = fmaxf(cmax, __shfl_xor_sync(0xffffffffu, cmax, 1));
        cmax = fmaxf(cmax, __shfl_xor_sync(0xffffffffu, cmax, 2));
        float newm = fmaxf(m, cmax);
        float alpha = __expf(m - newm);
        float psum = 0.f;
#pragma unroll
        for (int kk = 0; kk < 8; kk++) {
            float p = __expf(s[kk] - newm);
            Ps[tq][kk * 4 + part] = p;
            psum += p;
        }
        psum += __shfl_xor_sync(0xffffffffu, psum, 1);
        psum += __shfl_xor_sync(0xffffffffu, psum, 2);
        lsum = lsum * alpha + psum;
        m = newm;
#pragma unroll
        for (int d = 0; d < 16; d++) acc[d] *= alpha;
        __syncwarp();
        if (psum > 0.f) {
#pragma unroll
            for (int key = 0; key < 32; key++) {
                float p = Ps[tq][key];
#pragma unroll
                for (int c = 0; c < 16; c += 4) {
                    float4 v = *(const float4*)&Vs[key][part * 16 + c];
                    acc[c]     += p * v.x; acc[c + 1] += p * v.y;
                    acc[c + 2] += p * v.z; acc[c + 3] += p * v.w;
                }
            }
        }
    }

    float inv = (lsum > 0.f) ? 1.f / lsum : 0.f;
    long long ob = ((long long)b * LSEQ + i_row) * 1024 + h * 64 + part * 16;
#pragma unroll
    for (int c = 0; c < 16; c += 4) {
        float4 v = make_float4(acc[c] * inv, acc[c + 1] * inv, acc[c + 2] * inv, acc[c + 3] * inv);
        *(float4*)(out + ob + c) = v;
    }
}

// ===================== fused residual-add + LayerNorm =====================
__global__ void __launch_bounds__(256) add_ln_kernel(
    float* __restrict__ x, const float* __restrict__ r,
    const float* __restrict__ g, const float* __restrict__ bta, int layer)
{
    __shared__ float s1[8], s2[8];
    int row = blockIdx.x;
    int z = row >> 10;
    const float* gg = g   + ((long long)z * NLAYER + layer) * 1024;
    const float* bb = bta + ((long long)z * NLAYER + layer) * 1024;
    float* xr = x + (long long)row * 1024;
    const float* rr = r + (long long)row * 1024;
    int tid = threadIdx.x;

    float4 xv = *(const float4*)(xr + tid * 4);
    float4 rv = *(const float4*)(rr + tid * 4);
    float v0 = xv.x + rv.x, v1 = xv.y + rv.y, v2 = xv.z + rv.z, v3 = xv.w + rv.w;
    float sum = v0 + v1 + v2 + v3;
    float sq  = v0 * v0 + v1 * v1 + v2 * v2 + v3 * v3;
#pragma unroll
    for (int o = 16; o; o >>= 1) {
        sum += __shfl_xor_sync(0xffffffffu, sum, o);
        sq  += __shfl_xor_sync(0xffffffffu, sq,  o);
    }
    if ((tid & 31) == 0) { s1[tid >> 5] = sum; s2[tid >> 5] = sq; }
    __syncthreads();
    if (tid < 32) {
        sum = (tid < 8) ? s1[tid] : 0.f;
        sq  = (tid < 8) ? s2[tid] : 0.f;
#pragma unroll
        for (int o = 4; o; o >>= 1) {
            sum += __shfl_xor_sync(0xffffffffu, sum, o);
            sq  += __shfl_xor_sync(0xffffffffu, sq,  o);
        }
        if (tid == 0) { s1[0] = sum; s2[0] = sq; }
    }
    __syncthreads();
    float mean = s1[0] * (1.f / 1024.f);
    float var  = s2[0] * (1.f / 1024.f) - mean * mean;
    float rstd = rsqrtf(var + 1e-5f);
    float4 gv = *(const float4*)(gg + tid * 4);
    float4 bv = *(const float4*)(bb + tid * 4);
    float4 o;
    o.x = (v0 - mean) * rstd * gv.x + bv.x;
    o.y = (v1 - mean) * rstd * gv.y + bv.y;
    o.z = (v2 - mean) * rstd * gv.z + bv.z;
    o.w = (v3 - mean) * rstd * gv.w + bv.w;
    *(float4*)(xr + tid * 4) = o;
}

// ===================== fusion attention =====================
__global__ void __launch_bounds__(256) fuse_score_kernel(
    const float* __restrict__ t, const float* __restrict__ v, float* __restrict__ s)
{
    __shared__ float red[8];
    int l = blockIdx.x, k = blockIdx.y, tid = threadIdx.x;
    const float* row = t + ((long long)k * LSEQ + l) * 1024;
    float4 a = *(const float4*)(row + tid * 4);
    float4 b = *(const float4*)(v + tid * 4);
    float p = tanhf(a.x) * b.x + tanhf(a.y) * b.y + tanhf(a.z) * b.z + tanhf(a.w) * b.w;
#pragma unroll
    for (int o = 16; o; o >>= 1) p += __shfl_xor_sync(0xffffffffu, p, o);
    if ((tid & 31) == 0) red[tid >> 5] = p;
    __syncthreads();
    if (tid < 32) {
        p = (tid < 8) ? red[tid] : 0.f;
#pragma unroll
        for (int o = 4; o; o >>= 1) p += __shfl_xor_sync(0xffffffffu, p, o);
        if (tid == 0) s[(long long)k * LSEQ + l] = p;
    }
}

__global__ void __launch_bounds__(256) fuse_combine_kernel(
    const float* __restrict__ h0, const float* __restrict__ h1,
    const float* __restrict__ s, float* __restrict__ out)
{
    int l = blockIdx.x, tid = threadIdx.x;
    float s0 = s[l], s1 = s[LSEQ + l];
    float mm = fmaxf(s0, s1);
    float e0 = __expf(s0 - mm), e1 = __expf(s1 - mm);
    float inv = 1.f / (e0 + e1);
    float w0 = e0 * inv, w1 = e1 * inv;
    float4 a = *(const float4*)(h0 + (long long)l * 1024 + tid * 4);
    float4 b = *(const float4*)(h1 + (long long)l * 1024 + tid * 4);
    float4 o;
    o.x = w0 * a.x + w1 * b.x; o.y = w0 * a.y + w1 * b.y;
    o.z = w0 * a.z + w1 * b.z; o.w = w0 * a.w + w1 * b.w;
    *(float4*)(out + (long long)l * 1024 + tid * 4) = o;
}

// ===================== classifier + log_softmax =====================
__global__ void __launch_bounds__(256) classify_kernel(
    const float* __restrict__ x, const float* __restrict__ Wc,
    const float* __restrict__ bc, float* __restrict__ out)
{
    __shared__ float red[8][8];
    int l = blockIdx.x, tid = threadIdx.x;
    const float* row = x + (long long)l * 1024;
    float p[NCLS];
#pragma unroll
    for (int c = 0; c < NCLS; c++) p[c] = 0.f;
    for (int d = tid; d < 1024; d += 256) {
        float xv = row[d];
#pragma unroll
        for (int c = 0; c < NCLS; c++) p[c] += xv * Wc[d * NCLS + c];
    }
#pragma unroll
    for (int c = 0; c < NCLS; c++)
#pragma unroll
        for (int o = 16; o; o >>= 1) p[c] += __shfl_xor_sync(0xffffffffu, p[c], o);
    if ((tid & 31) == 0)
#pragma unroll
        for (int c = 0; c < NCLS; c++) red[tid >> 5][c] = p[c];
    __syncthreads();
    if (tid == 0) {
        float lg[NCLS];
#pragma unroll
        for (int c = 0; c < NCLS; c++) {
            float a = bc[c];
#pragma unroll
            for (int w = 0; w < 8; w++) a += red[w][c];
            lg[c] = a;
        }
        float mm = lg[0];
#pragma unroll
        for (int c = 1; c < NCLS; c++) mm = fmaxf(mm, lg[c]);
        float se = 0.f;
#pragma unroll
        for (int c = 0; c < NCLS; c++) se += expf(lg[c] - mm);
        float lse = mm + logf(se);
#pragma unroll
        for (int c = 0; c < NCLS; c++) out[(long long)l * NCLS + c] = lg[c] - lse;
    }
}

// ===================== orchestration =====================
extern "C" void kernel_launch(void* const* d_in, const int* in_sizes, int n_in,
                              void* d_out, int out_size)
{
    const float* src  = (const float*)d_in[0];
    const int*   utt  = (const int*)d_in[1];
    const int*   spk  = (const int*)d_in[2];
    const int*   win  = (const int*)d_in[3];
    const float* Wqkv = (const float*)d_in[4];
    const float* bqkv = (const float*)d_in[5];
    const float* Wo   = (const float*)d_in[6];
    const float* bo   = (const float*)d_in[7];
    const float* ln1g = (const float*)d_in[8];
    const float* ln1b = (const float*)d_in[9];
    const float* Wf1  = (const float*)d_in[10];
    const float* bf1  = (const float*)d_in[11];
    const float* Wf2  = (const float*)d_in[12];
    const float* bf2  = (const float*)d_in[13];
    const float* ln2g = (const float*)d_in[14];
    const float* ln2b = (const float*)d_in[15];
    const float* f1W  = (const float*)d_in[16];
    const float* f1b  = (const float*)d_in[17];
    const float* f1v  = (const float*)d_in[18];
    const float* f2W  = (const float*)d_in[19];
    const float* f2b  = (const float*)d_in[20];
    const float* f2v  = (const float*)d_in[21];
    const float* clsW = (const float*)d_in[22];
    const float* clsb = (const float*)d_in[23];

    float *x, *qkv, *attn, *t1, *t2, *sc, *sp, *fo;
    cudaGetSymbolAddress((void**)&x,    g_x);
    cudaGetSymbolAddress((void**)&qkv,  g_qkv);
    cudaGetSymbolAddress((void**)&attn, g_attn);
    cudaGetSymbolAddress((void**)&t1,   g_t1);
    cudaGetSymbolAddress((void**)&t2,   g_t2);
    cudaGetSymbolAddress((void**)&sc,   g_sc);
    cudaGetSymbolAddress((void**)&sp,   g_sp);
    cudaGetSymbolAddress((void**)&fo,   g_fo);

    __nv_bfloat16 *wqkvTh, *wqkvTl, *woTh, *woTl, *wf1Th, *wf1Tl, *wf2Th, *wf2Tl;
    __nv_bfloat16 *f1wTh, *f1wTl, *f2wTh, *f2wTl;
    cudaGetSymbolAddress((void**)&wqkvTh, g_wqkvT_h);
    cudaGetSymbolAddress((void**)&wqkvTl, g_wqkvT_l);
    cudaGetSymbolAddress((void**)&woTh,   g_woT_h);
    cudaGetSymbolAddress((void**)&woTl,   g_woT_l);
    cudaGetSymbolAddress((void**)&wf1Th,  g_wf1T_h);
    cudaGetSymbolAddress((void**)&wf1Tl,  g_wf1T_l);
    cudaGetSymbolAddress((void**)&wf2Th,  g_wf2T_h);
    cudaGetSymbolAddress((void**)&wf2Tl,  g_wf2T_l);
    cudaGetSymbolAddress((void**)&f1wTh,  g_f1wT_h);
    cudaGetSymbolAddress((void**)&f1wTl,  g_f1wT_l);
    cudaGetSymbolAddress((void**)&f2wTh,  g_f2wT_h);
    cudaGetSymbolAddress((void**)&f2wTl,  g_f2wT_l);

    cudaFuncSetAttribute(hmma_gemm_kernel, cudaFuncAttributeMaxDynamicSharedMemorySize,
                         GEMM_SMEM_BYTES);

    const long long LD = (long long)LSEQ * DMODEL;
    dim3 tb(32, 8);

    // weight conversion (transpose + bf16 hi/lo split)
    transpose_split_kernel<<<dim3(96, 32, 9),   tb>>>(Wqkv, wqkvTh, wqkvTl, 1024, 3072);
    transpose_split_kernel<<<dim3(32, 32, 9),   tb>>>(Wo,   woTh,   woTl,   1024, 1024);
    transpose_split_kernel<<<dim3(128, 32, 9),  tb>>>(Wf1,  wf1Th,  wf1Tl,  1024, 4096);
    transpose_split_kernel<<<dim3(32, 128, 9),  tb>>>(Wf2,  wf2Th,  wf2Tl,  4096, 1024);
    transpose_split_kernel<<<dim3(32, 32, 1),   tb>>>(f1W,  f1wTh,  f1wTl,  1024, 1024);
    transpose_split_kernel<<<dim3(32, 32, 1),   tb>>>(f2W,  f2wTh,  f2wTl,  1024, 1024);

    add_pe_kernel<<<LSEQ * DMODEL / 256, 256>>>(src, x);

    for (int l = 0; l < NLAYER; l++) {
        // QKV: [L,1024] x W[1024,3072]
        hmma_gemm_kernel<<<dim3(24, 8, 3), 256, GEMM_SMEM_BYTES>>>(
            x, LD,
            wqkvTh + (long long)l * 3072 * 1024, wqkvTl + (long long)l * 3072 * 1024,
            (long long)NLAYER * 3072 * 1024,
            bqkv + (long long)l * 3072, (long long)NLAYER * 3072,
            qkv, (long long)LSEQ * 3072, 3072, 1024, 0);

        attn_kernel<<<dim3(LSEQ / 64, NHEADS, 3), 256>>>(qkv, attn, utt, spk, win);

        hmma_gemm_kernel<<<dim3(8, 8, 3), 256, GEMM_SMEM_BYTES>>>(
            attn, LD,
            woTh + (long long)l * 1024 * 1024, woTl + (long long)l * 1024 * 1024,
            (long long)NLAYER * 1024 * 1024,
            bo + (long long)l * 1024, (long long)NLAYER * 1024,
            t2, LD, 1024, 1024, 0);

        add_ln_kernel<<<3 * LSEQ, 256>>>(x, t2, ln1g, ln1b, l);

        hmma_gemm_kernel<<<dim3(32, 8, 3), 256, GEMM_SMEM_BYTES>>>(
            x, LD,
            wf1Th + (long long)l * 4096 * 1024, wf1Tl + (long long)l * 4096 * 1024,
            (long long)NLAYER * 4096 * 1024,
            bf1 + (long long)l * 4096, (long long)NLAYER * 4096,
            t1, (long long)LSEQ * 4096, 4096, 1024, 1);

        hmma_gemm_kernel<<<dim3(8, 8, 3), 256, GEMM_SMEM_BYTES>>>(
            t1, (long long)LSEQ * 4096,
            wf2Th + (long long)l * 1024 * 4096, wf2Tl + (long long)l * 1024 * 4096,
            (long long)NLAYER * 1024 * 4096,
            bf2 + (long long)l * 1024, (long long)NLAYER * 1024,
            t2, LD, 1024, 4096, 0);

        add_ln_kernel<<<3 * LSEQ, 256>>>(x, t2, ln2g, ln2b, l);
    }

    // fusion 1: branches sm, om
    hmma_gemm_kernel<<<dim3(8, 8, 2), 256, GEMM_SMEM_BYTES>>>(
        x + LD, LD, f1wTh, f1wTl, 0, f1b, 0, t1, LD, 1024, 1024, 0);
    fuse_score_kernel<<<dim3(LSEQ, 2), 256>>>(t1, f1v, sc);
    fuse_combine_kernel<<<LSEQ, 256>>>(x + LD, x + 2 * LD, sc, sp);

    // fusion 2: ct, sp
    hmma_gemm_kernel<<<dim3(8, 8, 1), 256, GEMM_SMEM_BYTES>>>(
        x, 0, f2wTh, f2wTl, 0, f2b, 0, t1, 0, 1024, 1024, 0);
    hmma_gemm_kernel<<<dim3(8, 8, 1), 256, GEMM_SMEM_BYTES>>>(
        sp, 0, f2wTh, f2wTl, 0, f2b, 0, t1 + LD, 0, 1024, 1024, 0);
    fuse_score_kernel<<<dim3(LSEQ, 2), 256>>>(t1, f2v, sc);
    fuse_combine_kernel<<<LSEQ, 256>>>(x, sp, sc, fo);

    classify_kernel<<<LSEQ, 256>>>(fo, clsW, clsb, (float*)d_out);
}